// round 15
// baseline (speedup 1.0000x reference)
#include <cuda_runtime.h>
#include <cuda_fp16.h>
#include <cstdint>

// Problem-fixed maxima (setup_inputs: N=100000, E=1600000, F=H=128)
#define MAX_N 100000
#define MAX_E 1600000
#define CAP   96                     // per-node slot capacity; P(deg>96) < 1e-30

// -------- scratch (static device globals; no allocation) --------
__device__ __align__(16) int    g_srcdeg[MAX_N];
__device__ __align__(16) float  g_dinv[MAX_N];
__device__ __align__(16) int    g_cnt[MAX_N];            // in-degree (slot cursor)
__device__ int    g_tilectr;                             // GEMM work-stealing counter
__device__ __align__(16) int    g_slots[MAX_N * CAP];    // bucketed src lists (38.4 MB)
__device__ __align__(16) __half g_xh[MAX_N * 128];       // fp16 copy of x (25.6 MB)
__device__ __align__(16) __half g_aggh[MAX_N * 128];     // fp16 A_norm @ x (25.6 MB)
__device__ __align__(16) float  g_p[MAX_N];              // h . w2_0
__device__ __align__(16) float  g_g[MAX_N];              // dinv * (h . w2_1)

// ---------------- fused: bucket place + out-degree + fp16 convert ----------------
#define PU 4
__global__ __launch_bounds__(256) void k_placeconv(
    const float* __restrict__ x,
    const int* __restrict__ src, const int* __restrict__ dst,
    int E, int n)
{
    int tid = blockIdx.x * blockDim.x + threadIdx.x;
    int stride = gridDim.x * blockDim.x;

    // ---- phase A: place edges ----
    int base = tid * PU;
    if (base < E) {
        int s[PU], d[PU];
        #pragma unroll
        for (int u = 0; u < PU; ++u) {
            int e = base + u; e = (e < E) ? e : (E - 1);
            s[u] = __ldg(&src[e]); d[u] = __ldg(&dst[e]);
        }
        #pragma unroll
        for (int u = 0; u < PU; ++u) {
            if (base + u < E) {
                atomicAdd(&g_srcdeg[s[u]], 1);
                int pos = atomicAdd(&g_cnt[d[u]], 1);
                if (pos < CAP) g_slots[d[u] * CAP + pos] = s[u];
            }
        }
    }

    // ---- phase B: convert x -> fp16 (grid-stride) ----
    const float2* x2 = (const float2*)x;
    __half2* xh2 = (__half2*)g_xh;
    int tot = n * 64;
    for (int i = tid; i < tot; i += stride) {
        float2 v = x2[i];
        xh2[i] = __floats2half2_rn(v.x, v.y);
    }
}

__global__ void k_dinv(int n) {
    int i = blockIdx.x * blockDim.x + threadIdx.x;
    if (i == 0) g_tilectr = 0;
    if (i < n) {
        int d = g_srcdeg[i];
        g_dinv[i] = (d > 0) ? rsqrtf((float)d) : 0.f;
    }
}

// ---------------- layer-1 gather (R10-proven version) ----------------
__global__ __launch_bounds__(256) void k_gather(int n) {
    int node = (blockIdx.x * blockDim.x + threadIdx.x) >> 5;
    int lane = threadIdx.x & 31;
    if (node >= n) return;
    int half = lane >> 4;
    int fl = lane & 15;
    const uint4* xh = (const uint4*)g_xh;
    int deg = __ldg(&g_cnt[node]);
    deg = (deg < CAP) ? deg : CAP;
    int beg = node * CAP;
    int end = beg + deg;
    float acc[8];
    #pragma unroll
    for (int j = 0; j < 8; ++j) acc[j] = 0.f;

    int e = beg;
    for (; e + 8 <= end; e += 8) {
        int s[4];
        #pragma unroll
        for (int u = 0; u < 4; ++u) s[u] = __ldg(&g_slots[e + 2 * u + half]);
        uint4 r[4];
        #pragma unroll
        for (int u = 0; u < 4; ++u) r[u] = xh[(size_t)s[u] * 16 + fl];
        float w[4];
        #pragma unroll
        for (int u = 0; u < 4; ++u) w[u] = __ldg(&g_dinv[s[u]]);
        #pragma unroll
        for (int u = 0; u < 4; ++u) {
            const __half2* h2 = (const __half2*)&r[u];
            #pragma unroll
            for (int j = 0; j < 4; ++j) {
                float2 f = __half22float2(h2[j]);
                acc[2 * j]     = fmaf(w[u], f.x, acc[2 * j]);
                acc[2 * j + 1] = fmaf(w[u], f.y, acc[2 * j + 1]);
            }
        }
    }
    for (; e < end; e += 2) {
        int idx = e + half;
        if (idx < end) {
            int s = __ldg(&g_slots[idx]);
            uint4 r = xh[(size_t)s * 16 + fl];
            float w = __ldg(&g_dinv[s]);
            const __half2* h2 = (const __half2*)&r;
            #pragma unroll
            for (int j = 0; j < 4; ++j) {
                float2 f = __half22float2(h2[j]);
                acc[2 * j]     = fmaf(w, f.x, acc[2 * j]);
                acc[2 * j + 1] = fmaf(w, f.y, acc[2 * j + 1]);
            }
        }
    }
    #pragma unroll
    for (int j = 0; j < 8; ++j)
        acc[j] += __shfl_xor_sync(0xffffffffu, acc[j], 16);

    if (half == 0) {
        float sc = -__ldg(&g_dinv[node]);
        uint4 o;
        __half2* oh = (__half2*)&o;
        #pragma unroll
        for (int j = 0; j < 4; ++j)
            oh[j] = __floats2half2_rn(sc * acc[2 * j], sc * acc[2 * j + 1]);
        ((uint4*)g_aggh)[(size_t)node * 16 + fl] = o;
    }
}

// ---------------- HMMA / async helpers ----------------
__device__ __forceinline__ void ldsm_x4(uint32_t* r, uint32_t addr) {
    asm volatile("ldmatrix.sync.aligned.m8n8.x4.shared.b16 {%0,%1,%2,%3}, [%4];"
                 : "=r"(r[0]), "=r"(r[1]), "=r"(r[2]), "=r"(r[3]) : "r"(addr));
}
__device__ __forceinline__ void ldsm_x2t(uint32_t* r, uint32_t addr) {
    asm volatile("ldmatrix.sync.aligned.m8n8.x2.trans.shared.b16 {%0,%1}, [%2];"
                 : "=r"(r[0]), "=r"(r[1]) : "r"(addr));
}
__device__ __forceinline__ void mma16816(float* d, const uint32_t* a, const uint32_t* b) {
    asm volatile(
        "mma.sync.aligned.m16n8k16.row.col.f32.f16.f16.f32 "
        "{%0,%1,%2,%3}, {%4,%5,%6,%7}, {%8,%9}, {%0,%1,%2,%3};"
        : "+f"(d[0]), "+f"(d[1]), "+f"(d[2]), "+f"(d[3])
        : "r"(a[0]), "r"(a[1]), "r"(a[2]), "r"(a[3]), "r"(b[0]), "r"(b[1]));
}
__device__ __forceinline__ void cp_async16(uint32_t saddr, const void* gptr) {
    asm volatile("cp.async.cg.shared.global [%0], [%1], 16;"
                 :: "r"(saddr), "l"(gptr) : "memory");
}
#define CP_COMMIT() asm volatile("cp.async.commit_group;" ::: "memory")
#define CP_WAIT1()  asm volatile("cp.async.wait_group 1;" ::: "memory")
#define CP_WAIT0()  asm volatile("cp.async.wait_group 0;" ::: "memory")

// smem layout (halves / floats)
#define B_STRIDE 136          // halves per k-row of B (128 + 8 pad)
#define A_STRIDE 264          // halves per m-row of A (256 + 8 pad); 528 B, 16B-aligned
#define SM_B_HALVES (256 * B_STRIDE)
#define SM_A_HALVES (128 * A_STRIDE)
#define SMEM_GEMM_BYTES (SM_B_HALVES * 2 + SM_A_HALVES * 2 + (128 * 3 + 512 + 512) * 4)

// ---------------- persistent tensor-core GEMM + epilogue (16 warps) --------------
// Z = [x_h | agg_h] @ [w1_0 ; w1_1]  (M=n, K=256, N=128)
// h = relu(Z + b1);  p = h.w2_0;  g = dinv * (h.w2_1)
// 512 threads = 4x4 warps, warp tile 32x32 (2 mt x 4 nt of m16n8k16).
// Split-phase A load: x-half and agg-half in separate cp.async groups;
// kc 0..7 (x-half) overlaps the in-flight agg-half load.
__global__ __launch_bounds__(512, 1) void k_gemm(
    const float* __restrict__ w10, const float* __restrict__ w11,
    const float* __restrict__ b1,
    const float* __restrict__ w20, const float* __restrict__ w21, int n)
{
    extern __shared__ __align__(16) char smraw[];
    __half* Bs = (__half*)smraw;                 // [256][136]
    __half* As = Bs + SM_B_HALVES;               // [128][264]
    float* sb1 = (float*)(As + SM_A_HALVES);     // [128]
    float* sw20 = sb1 + 128;
    float* sw21 = sw20 + 128;
    float* sP = sw21 + 128;                      // [4][128]
    float* sG = sP + 512;                        // [4][128]
    __shared__ int sTile;

    int tid = threadIdx.x;
    int w = tid >> 5, lane = tid & 31;
    int wm = w >> 2, wn = w & 3;                 // 4x4 warp grid
    int mwarp = wm * 32;
    int nwarp = wn * 32;

    // ---- convert weights fp32 -> fp16 into padded smem (once per block) ----
    {
        int r = tid >> 2, q = tid & 3;           // k-row 0..127, col quarter
        const float* s0 = w10 + (size_t)r * 128 + q * 32;
        const float* s1 = w11 + (size_t)r * 128 + q * 32;
        uint2* d0 = (uint2*)(Bs + r * B_STRIDE + q * 32);
        uint2* d1 = (uint2*)(Bs + (r + 128) * B_STRIDE + q * 32);
        #pragma unroll
        for (int i = 0; i < 8; ++i) {
            float4 v = ((const float4*)s0)[i];
            uint2 o;
            *(__half2*)&o.x = __floats2half2_rn(v.x, v.y);
            *(__half2*)&o.y = __floats2half2_rn(v.z, v.w);
            d0[i] = o;
            v = ((const float4*)s1)[i];
            *(__half2*)&o.x = __floats2half2_rn(v.x, v.y);
            *(__half2*)&o.y = __floats2half2_rn(v.z, v.w);
            d1[i] = o;
        }
    }
    if (tid < 128) { sb1[tid] = b1[tid]; sw20[tid] = w20[tid]; sw21[tid] = w21[tid]; }

    uint32_t aBase = (uint32_t)__cvta_generic_to_shared(As);
    uint32_t bBase = (uint32_t)__cvta_generic_to_shared(Bs);
    int aRowOff = (lane & 15) * A_STRIDE + (lane >> 4) * 8;
    int bRowOff = (lane & 15) * B_STRIDE;

    int ntiles = (n + 127) >> 7;
    int i0 = tid & 15;          // 16B chunk within a 256B half-row
    int rw = tid >> 4;          // base row (32 rows per pass)

    while (true) {
        if (tid == 0) sTile = atomicAdd(&g_tilectr, 1);
        __syncthreads();
        int tile = sTile;
        if (tile >= ntiles) break;
        int m0 = tile << 7;

        // ---- async A-tile load: group 1 = x-half, group 0 = agg-half ----
        int rowc[4];
        #pragma unroll
        for (int pass = 0; pass < 4; ++pass) {
            int row = rw + pass * 32;
            int gm = m0 + row;
            rowc[pass] = (gm < n) ? gm : (n - 1);
            cp_async16(aBase + 2u * (row * A_STRIDE) + i0 * 16,
                       (const char*)(g_xh + (size_t)rowc[pass] * 128) + i0 * 16);
        }
        CP_COMMIT();
        #pragma unroll
        for (int pass = 0; pass < 4; ++pass) {
            int row = rw + pass * 32;
            cp_async16(aBase + 2u * (row * A_STRIDE + 128) + i0 * 16,
                       (const char*)(g_aggh + (size_t)rowc[pass] * 128) + i0 * 16);
        }
        CP_COMMIT();

        float dacc[2][4][4];
        #pragma unroll
        for (int mt = 0; mt < 2; ++mt)
            #pragma unroll
            for (int nt = 0; nt < 4; ++nt)
                #pragma unroll
                for (int j = 0; j < 4; ++j) dacc[mt][nt][j] = 0.f;

        CP_WAIT1();             // x-half resident; agg-half may still be in flight
        __syncthreads();

        // ---- kc 0..7: x-half of A ----
        #pragma unroll 1
        for (int kc = 0; kc < 8; ++kc) {
            uint32_t af[2][4], bf[4][2];
            #pragma unroll
            for (int mt = 0; mt < 2; ++mt)
                ldsm_x4(af[mt], aBase + 2u * ((mwarp + 16 * mt) * A_STRIDE + aRowOff + kc * 16));
            #pragma unroll
            for (int nt = 0; nt < 4; ++nt)
                ldsm_x2t(bf[nt], bBase + 2u * (kc * 16 * B_STRIDE + bRowOff + nwarp + nt * 8));
            #pragma unroll
            for (int mt = 0; mt < 2; ++mt)
                #pragma unroll
                for (int nt = 0; nt < 4; ++nt)
                    mma16816(dacc[mt][nt], af[mt], bf[nt]);
        }

        CP_WAIT0();             // agg-half resident
        __syncthreads();

        // ---- kc 8..15: agg-half of A ----
        #pragma unroll 1
        for (int kc = 8; kc < 16; ++kc) {
            uint32_t af[2][4], bf[4][2];
            #pragma unroll
            for (int mt = 0; mt < 2; ++mt)
                ldsm_x4(af[mt], aBase + 2u * ((mwarp + 16 * mt) * A_STRIDE + aRowOff + kc * 16));
            #pragma unroll
            for (int nt = 0; nt < 4; ++nt)
                ldsm_x2t(bf[nt], bBase + 2u * (kc * 16 * B_STRIDE + bRowOff + nwarp + nt * 8));
            #pragma unroll
            for (int mt = 0; mt < 2; ++mt)
                #pragma unroll
                for (int nt = 0; nt < 4; ++nt)
                    mma16816(dacc[mt][nt], af[mt], bf[nt]);
        }

        // ---- epilogue: bias+relu+dot, reduce over 4-lane col groups ----
        #pragma unroll
        for (int ri = 0; ri < 4; ++ri) {
            int mt = ri >> 1, hi = ri & 1;
            float p = 0.f, g = 0.f;
            #pragma unroll
            for (int nt = 0; nt < 4; ++nt) {
                #pragma unroll
                for (int cc = 0; cc < 2; ++cc) {
                    int c = nwarp + nt * 8 + 2 * (lane & 3) + cc;
                    float h = fmaxf(dacc[mt][nt][2 * hi + cc] + sb1[c], 0.f);
                    p = fmaf(h, sw20[c], p);
                    g = fmaf(h, sw21[c], g);
                }
            }
            p += __shfl_xor_sync(0xffffffffu, p, 1);
            p += __shfl_xor_sync(0xffffffffu, p, 2);
            g += __shfl_xor_sync(0xffffffffu, g, 1);
            g += __shfl_xor_sync(0xffffffffu, g, 2);
            if ((lane & 3) == 0) {
                int lrow = mwarp + 16 * mt + 8 * hi + (lane >> 2);
                sP[wn * 128 + lrow] = p;
                sG[wn * 128 + lrow] = g;
            }
        }
        __syncthreads();
        if (tid < 128) {
            int m = m0 + tid;
            if (m < n) {
                g_p[m] = sP[tid] + sP[128 + tid] + sP[256 + tid] + sP[384 + tid];
                g_g[m] = (sG[tid] + sG[128 + tid] + sG[256 + tid] + sG[384 + tid])
                         * g_dinv[m];   // pre-scale by dinv
            }
        }
        __syncthreads();
    }
}

// ---------------- layer-2 gather + output ----------------
// out[d] = sigmoid(p[d] - dinv[d] * sum_e g[src_e] + b2)
__global__ __launch_bounds__(256) void k_gather2(const float* __restrict__ b2,
                                                 float* __restrict__ out, int n) {
    int node = (blockIdx.x * blockDim.x + threadIdx.x) >> 5;
    int lane = threadIdx.x & 31;
    if (node >= n) return;
    int deg = __ldg(&g_cnt[node]);
    deg = (deg < CAP) ? deg : CAP;
    int beg = node * CAP;
    int end = beg + deg;
    float a = 0.f;
    for (int e = beg + lane; e < end; e += 32)
        a += __ldg(&g_g[__ldg(&g_slots[e])]);
    #pragma unroll
    for (int off = 16; off >= 1; off >>= 1)
        a += __shfl_xor_sync(0xffffffffu, a, off);
    if (lane == 0) {
        float z = __ldg(&g_p[node]) - __ldg(&g_dinv[node]) * a + b2[0];
        out[node] = 1.0f / (1.0f + expf(-z));
    }
}

extern "C" void kernel_launch(void* const* d_in, const int* in_sizes, int n_in,
                              void* d_out, int out_size) {
    const float* x   = (const float*)d_in[0];
    const int*   ei  = (const int*)d_in[1];
    const float* w10 = (const float*)d_in[2];
    const float* w11 = (const float*)d_in[3];
    const float* b1  = (const float*)d_in[4];
    const float* w20 = (const float*)d_in[5];
    const float* w21 = (const float*)d_in[6];
    const float* b2  = (const float*)d_in[7];
    float* out = (float*)d_out;

    int n = in_sizes[0] / 128;
    int E = in_sizes[1] / 2;
    const int* src = ei;
    const int* dst = ei + E;

    // zero the two counter arrays (memset nodes; no kernel needed)
    void* p_cnt = nullptr;
    void* p_srcdeg = nullptr;
    cudaGetSymbolAddress(&p_cnt, g_cnt);
    cudaGetSymbolAddress(&p_srcdeg, g_srcdeg);
    cudaMemsetAsync(p_cnt, 0, (size_t)n * sizeof(int));
    cudaMemsetAsync(p_srcdeg, 0, (size_t)n * sizeof(int));

    int pblocks = (E + 256 * PU - 1) / (256 * PU);
    k_placeconv<<<pblocks, 256>>>(x, src, dst, E, n);
    k_dinv<<<(n + 255) / 256, 256>>>(n);
    k_gather<<<(n * 32 + 255) / 256, 256>>>(n);

    cudaFuncSetAttribute(k_gemm, cudaFuncAttributeMaxDynamicSharedMemorySize,
                         SMEM_GEMM_BYTES);
    k_gemm<<<152, 512, SMEM_GEMM_BYTES>>>(w10, w11, b1, w20, w21, n);

    k_gather2<<<(n * 32 + 255) / 256, 256>>>(b2, out, n);
}

// round 16
// speedup vs baseline: 1.0795x; 1.0795x over previous
#include <cuda_runtime.h>
#include <cuda_fp16.h>
#include <cstdint>

// Problem-fixed maxima (setup_inputs: N=100000, E=1600000, F=H=128)
#define MAX_N 100000
#define MAX_E 1600000
#define CAP   96                     // per-node slot capacity; P(deg>96) < 1e-30
#define PADROWS 128                  // tile overrun padding for bulk copies

// -------- scratch (static device globals; no allocation) --------
// g_xh / g_aggh / g_wh are stored SWIZZLED: 256 B rows of 16 chunks (16 B),
// chunk c of row r lives at slot c ^ (r & 7). Contiguous 128-row tiles are
// bulk-copyable into smem and ldmatrix-conflict-free.
__device__ __align__(16) int    g_srcdeg[MAX_N];
__device__ __align__(16) float  g_dinv[MAX_N];
__device__ __align__(16) int    g_cnt[MAX_N];            // in-degree (slot cursor)
__device__ int    g_tilectr;                             // GEMM work-stealing counter
__device__ __align__(16) int    g_slots[MAX_N * CAP];    // bucketed src lists (38.4 MB)
__device__ __align__(16) __half g_xh[(MAX_N + PADROWS) * 128];   // fp16 x (swizzled)
__device__ __align__(16) __half g_aggh[(MAX_N + PADROWS) * 128]; // fp16 agg (swizzled)
__device__ __align__(16) __half g_wh[256 * 128];         // fp16 [w1_0;w1_1] (swizzled)
__device__ __align__(16) float  g_p[MAX_N];              // h . w2_0
__device__ __align__(16) float  g_g[MAX_N];              // dinv * (h . w2_1)

// ---------------- fused: bucket place + out-degree + fp16 converts --------------
#define PU 4
__global__ __launch_bounds__(256) void k_placeconv(
    const float* __restrict__ x,
    const float* __restrict__ w10, const float* __restrict__ w11,
    const int* __restrict__ src, const int* __restrict__ dst,
    int E, int n)
{
    int tid = blockIdx.x * blockDim.x + threadIdx.x;
    int stride = gridDim.x * blockDim.x;

    // ---- phase A: place edges ----
    int base = tid * PU;
    if (base < E) {
        int s[PU], d[PU];
        #pragma unroll
        for (int u = 0; u < PU; ++u) {
            int e = base + u; e = (e < E) ? e : (E - 1);
            s[u] = __ldg(&src[e]); d[u] = __ldg(&dst[e]);
        }
        #pragma unroll
        for (int u = 0; u < PU; ++u) {
            if (base + u < E) {
                atomicAdd(&g_srcdeg[s[u]], 1);
                int pos = atomicAdd(&g_cnt[d[u]], 1);
                if (pos < CAP) g_slots[d[u] * CAP + pos] = s[u];
            }
        }
    }

    // ---- phase B: x -> fp16, swizzled chunk layout ----
    uint4* xh4 = (uint4*)g_xh;
    int totc = n * 16;
    for (int i = tid; i < totc; i += stride) {
        int row = i >> 4, c = i & 15;
        const float4* xr = (const float4*)(x + (size_t)row * 128);
        float4 v0 = __ldg(&xr[c * 2]);
        float4 v1 = __ldg(&xr[c * 2 + 1]);
        uint4 o;
        __half2* oh = (__half2*)&o;
        oh[0] = __floats2half2_rn(v0.x, v0.y);
        oh[1] = __floats2half2_rn(v0.z, v0.w);
        oh[2] = __floats2half2_rn(v1.x, v1.y);
        oh[3] = __floats2half2_rn(v1.z, v1.w);
        xh4[(size_t)row * 16 + (c ^ (row & 7))] = o;
    }

    // ---- phase C: weights -> fp16, swizzled (B[k][col]; k<128 w10, else w11) ----
    uint4* wh4 = (uint4*)g_wh;
    for (int i = tid; i < 256 * 16; i += stride) {
        int k = i >> 4, c = i & 15;
        const float* wsrc = (k < 128) ? (w10 + (size_t)k * 128 + c * 8)
                                      : (w11 + (size_t)(k - 128) * 128 + c * 8);
        float4 v0 = __ldg((const float4*)wsrc);
        float4 v1 = __ldg((const float4*)(wsrc + 4));
        uint4 o;
        __half2* oh = (__half2*)&o;
        oh[0] = __floats2half2_rn(v0.x, v0.y);
        oh[1] = __floats2half2_rn(v0.z, v0.w);
        oh[2] = __floats2half2_rn(v1.x, v1.y);
        oh[3] = __floats2half2_rn(v1.z, v1.w);
        wh4[k * 16 + (c ^ (k & 7))] = o;
    }
}

__global__ void k_dinv(int n) {
    int i = blockIdx.x * blockDim.x + threadIdx.x;
    if (i == 0) g_tilectr = 0;
    if (i < n) {
        int d = g_srcdeg[i];
        g_dinv[i] = (d > 0) ? rsqrtf((float)d) : 0.f;
    }
}

// ---------------- layer-1 gather (R10 body; swizzled chunk indexing) ------------
__global__ __launch_bounds__(256) void k_gather(int n) {
    int node = (blockIdx.x * blockDim.x + threadIdx.x) >> 5;
    int lane = threadIdx.x & 31;
    if (node >= n) return;
    int half = lane >> 4;
    int fl = lane & 15;
    const uint4* xh = (const uint4*)g_xh;
    int deg = __ldg(&g_cnt[node]);
    deg = (deg < CAP) ? deg : CAP;
    int beg = node * CAP;
    int end = beg + deg;
    float acc[8];
    #pragma unroll
    for (int j = 0; j < 8; ++j) acc[j] = 0.f;

    int e = beg;
    for (; e + 8 <= end; e += 8) {
        int s[4];
        #pragma unroll
        for (int u = 0; u < 4; ++u) s[u] = __ldg(&g_slots[e + 2 * u + half]);
        uint4 r[4];
        #pragma unroll
        for (int u = 0; u < 4; ++u)
            r[u] = xh[(size_t)s[u] * 16 + (fl ^ (s[u] & 7))];
        float w[4];
        #pragma unroll
        for (int u = 0; u < 4; ++u) w[u] = __ldg(&g_dinv[s[u]]);
        #pragma unroll
        for (int u = 0; u < 4; ++u) {
            const __half2* h2 = (const __half2*)&r[u];
            #pragma unroll
            for (int j = 0; j < 4; ++j) {
                float2 f = __half22float2(h2[j]);
                acc[2 * j]     = fmaf(w[u], f.x, acc[2 * j]);
                acc[2 * j + 1] = fmaf(w[u], f.y, acc[2 * j + 1]);
            }
        }
    }
    for (; e < end; e += 2) {
        int idx = e + half;
        if (idx < end) {
            int s = __ldg(&g_slots[idx]);
            uint4 r = xh[(size_t)s * 16 + (fl ^ (s & 7))];
            float w = __ldg(&g_dinv[s]);
            const __half2* h2 = (const __half2*)&r;
            #pragma unroll
            for (int j = 0; j < 4; ++j) {
                float2 f = __half22float2(h2[j]);
                acc[2 * j]     = fmaf(w, f.x, acc[2 * j]);
                acc[2 * j + 1] = fmaf(w, f.y, acc[2 * j + 1]);
            }
        }
    }
    #pragma unroll
    for (int j = 0; j < 8; ++j)
        acc[j] += __shfl_xor_sync(0xffffffffu, acc[j], 16);

    if (half == 0) {
        float sc = -__ldg(&g_dinv[node]);
        uint4 o;
        __half2* oh = (__half2*)&o;
        #pragma unroll
        for (int j = 0; j < 4; ++j)
            oh[j] = __floats2half2_rn(sc * acc[2 * j], sc * acc[2 * j + 1]);
        ((uint4*)g_aggh)[(size_t)node * 16 + (fl ^ (node & 7))] = o;
    }
}

// ---------------- HMMA / bulk-async helpers ----------------
__device__ __forceinline__ void ldsm_x4(uint32_t* r, uint32_t addr) {
    asm volatile("ldmatrix.sync.aligned.m8n8.x4.shared.b16 {%0,%1,%2,%3}, [%4];"
                 : "=r"(r[0]), "=r"(r[1]), "=r"(r[2]), "=r"(r[3]) : "r"(addr));
}
__device__ __forceinline__ void ldsm_x2t(uint32_t* r, uint32_t addr) {
    asm volatile("ldmatrix.sync.aligned.m8n8.x2.trans.shared.b16 {%0,%1}, [%2];"
                 : "=r"(r[0]), "=r"(r[1]) : "r"(addr));
}
__device__ __forceinline__ void mma16816(float* d, const uint32_t* a, const uint32_t* b) {
    asm volatile(
        "mma.sync.aligned.m16n8k16.row.col.f32.f16.f16.f32 "
        "{%0,%1,%2,%3}, {%4,%5,%6,%7}, {%8,%9}, {%0,%1,%2,%3};"
        : "+f"(d[0]), "+f"(d[1]), "+f"(d[2]), "+f"(d[3])
        : "r"(a[0]), "r"(a[1]), "r"(a[2]), "r"(a[3]), "r"(b[0]), "r"(b[1]));
}
__device__ __forceinline__ void bulk_cp(uint32_t dst, const void* src,
                                        uint32_t bytes, uint32_t mbar) {
    asm volatile(
        "cp.async.bulk.shared::cta.global.mbarrier::complete_tx::bytes [%0], [%1], %2, [%3];"
        :: "r"(dst), "l"(src), "r"(bytes), "r"(mbar) : "memory");
}
#define MBAR_INIT(a, c) \
    asm volatile("mbarrier.init.shared.b64 [%0], %1;" :: "r"(a), "r"(c) : "memory")
#define MBAR_EXPECT(a, b) \
    asm volatile("mbarrier.arrive.expect_tx.shared.b64 _, [%0], %1;" :: "r"(a), "r"(b) : "memory")
#define MBAR_WAIT(a, ph) do {                                                   \
    asm volatile("{\n\t.reg .pred P1;\n\t"                                      \
        "WL_%=:\n\tmbarrier.try_wait.parity.acquire.cta.shared::cta.b64 P1, [%0], %1, 0x989680;\n\t" \
        "@P1 bra.uni WD_%=;\n\tbra.uni WL_%=;\n\tWD_%=:\n\t}"                   \
        :: "r"(a), "r"(ph) : "memory"); } while (0)

// smem layout (bytes from 1024-aligned base)
#define SM_B_OFF   0            // 64 KB  weights (256 rows x 256 B, swizzled)
#define SM_A0_OFF  65536        // 64 KB  A buf 0 (x-half rows 0..127, agg rows 128..255)
#define SM_A1_OFF  131072       // 64 KB  A buf 1
#define SM_MISC    196608
#define SMEM_GEMM_BYTES (SM_MISC + 4096 + 64 + 1024)

// ---------------- persistent tensor-core GEMM + epilogue (8 warps) --------------
// Z = [x_h | agg_h] @ [w1_0 ; w1_1]  (M=n, K=256, N=128)
// h = relu(Z + b1);  p = h.w2_0;  g = dinv * (h.w2_1)
// Operand tiles arrive via cp.async.bulk (3 copies/tile, no per-thread LDGSTS).
__global__ __launch_bounds__(256, 1) void k_gemm(
    const float* __restrict__ b1,
    const float* __restrict__ w20, const float* __restrict__ w21, int n)
{
    extern __shared__ char smraw[];
    char* sm = (char*)(((uintptr_t)smraw + 1023) & ~(uintptr_t)1023);
    float* sb1  = (float*)(sm + SM_MISC);        // [128]
    float* sw20 = sb1 + 128;
    float* sw21 = sw20 + 128;
    float* sP   = sw21 + 128;                    // [2][128]
    float* sG   = sP + 256;                      // [2][128]
    unsigned long long* bars = (unsigned long long*)(sG + 256);  // [3]: A0, A1, B
    __shared__ int sTile;

    int tid = threadIdx.x;
    int w = tid >> 5, lane = tid & 31;
    int mwarp = (w >> 1) * 32;                   // 4 m-warps x 2 n-warps
    int nwarp = (w & 1) * 64;
    int nw8 = (w & 1) * 8;                       // B chunk base (cols/8)

    uint32_t bBase = (uint32_t)__cvta_generic_to_shared(sm + SM_B_OFF);
    uint32_t aB[2];
    aB[0] = (uint32_t)__cvta_generic_to_shared(sm + SM_A0_OFF);
    aB[1] = (uint32_t)__cvta_generic_to_shared(sm + SM_A1_OFF);
    uint32_t barA0 = (uint32_t)__cvta_generic_to_shared(&bars[0]);
    uint32_t barA1 = (uint32_t)__cvta_generic_to_shared(&bars[1]);
    uint32_t barB  = (uint32_t)__cvta_generic_to_shared(&bars[2]);

    if (tid == 0) {
        MBAR_INIT(barA0, 1);
        MBAR_INIT(barA1, 1);
        MBAR_INIT(barB, 1);
    }
    __syncthreads();

    // B tile: one 64 KB bulk copy per block
    if (tid == 0) {
        MBAR_EXPECT(barB, 65536);
        bulk_cp(bBase, g_wh, 65536, barB);
    }
    if (tid < 128) { sb1[tid] = b1[tid]; sw20[tid] = w20[tid]; sw21[tid] = w21[tid]; }

    int ntiles = (n + 127) >> 7;

    // steal tile 0 + start its A load
    if (tid == 0) sTile = atomicAdd(&g_tilectr, 1);
    __syncthreads();
    int tile = sTile;
    if (tile < ntiles && tid == 0) {
        MBAR_EXPECT(barA0, 65536);
        bulk_cp(aB[0], g_xh + (size_t)(tile << 7) * 128, 32768, barA0);
        bulk_cp(aB[0] + 32768, g_aggh + (size_t)(tile << 7) * 128, 32768, barA0);
    }

    MBAR_WAIT(barB, 0);          // weights resident

    int ph0 = 0, ph1 = 0, buf = 0;

    while (tile < ntiles) {
        int m0 = tile << 7;

        // steal + prefetch NEXT tile into the other buffer
        if (tid == 0) sTile = atomicAdd(&g_tilectr, 1);
        __syncthreads();         // also: all warps done reading buf^1 from last iter
        int next = sTile;
        if (next < ntiles && tid == 0) {
            uint32_t bar = (buf ^ 1) ? barA1 : barA0;
            MBAR_EXPECT(bar, 65536);
            bulk_cp(aB[buf ^ 1], g_xh + (size_t)(next << 7) * 128, 32768, bar);
            bulk_cp(aB[buf ^ 1] + 32768, g_aggh + (size_t)(next << 7) * 128, 32768, bar);
        }

        // wait current buffer
        if (buf == 0) { MBAR_WAIT(barA0, ph0); ph0 ^= 1; }
        else          { MBAR_WAIT(barA1, ph1); ph1 ^= 1; }

        float dacc[2][8][4];
        #pragma unroll
        for (int mt = 0; mt < 2; ++mt)
            #pragma unroll
            for (int nt = 0; nt < 8; ++nt)
                #pragma unroll
                for (int j = 0; j < 4; ++j) dacc[mt][nt][j] = 0.f;

        uint32_t aCur = aB[buf];
        int arow0 = lane & 15;       // row within 16-row ldsm group
        int asub = lane >> 4;        // 16B sub-chunk of the 32B k-chunk
        #pragma unroll 1
        for (int kc = 0; kc < 16; ++kc) {
            // A rows: kc<8 -> x-half (rows 0..127); kc>=8 -> agg-half (rows 128..255)
            int kcl = kc & 7;
            int rbase = (kc < 8) ? 0 : 128;
            uint32_t af[2][4], bf[8][2];
            #pragma unroll
            for (int mt = 0; mt < 2; ++mt) {
                int row = rbase + mwarp + 16 * mt + arow0;
                int ch = ((kcl << 1) | asub) ^ (row & 7);
                ldsm_x4(af[mt], aCur + row * 256 + ch * 16);
            }
            #pragma unroll
            for (int nt = 0; nt < 8; ++nt) {
                int row = kc * 16 + arow0;
                int ch = (nw8 + nt) ^ (row & 7);
                ldsm_x2t(bf[nt], bBase + row * 256 + ch * 16);
            }
            #pragma unroll
            for (int mt = 0; mt < 2; ++mt)
                #pragma unroll
                for (int nt = 0; nt < 8; ++nt)
                    mma16816(dacc[mt][nt], af[mt], bf[nt]);
        }

        // ---- epilogue: bias+relu+dot, reduce over 4-lane col groups ----
        #pragma unroll
        for (int ri = 0; ri < 4; ++ri) {
            int mt = ri >> 1, hi = ri & 1;
            float p = 0.f, g = 0.f;
            #pragma unroll
            for (int nt = 0; nt < 8; ++nt) {
                #pragma unroll
                for (int cc = 0; cc < 2; ++cc) {
                    int c = nwarp + nt * 8 + 2 * (lane & 3) + cc;
                    float h = fmaxf(dacc[mt][nt][2 * hi + cc] + sb1[c], 0.f);
                    p = fmaf(h, sw20[c], p);
                    g = fmaf(h, sw21[c], g);
                }
            }
            p += __shfl_xor_sync(0xffffffffu, p, 1);
            p += __shfl_xor_sync(0xffffffffu, p, 2);
            g += __shfl_xor_sync(0xffffffffu, g, 1);
            g += __shfl_xor_sync(0xffffffffu, g, 2);
            if ((lane & 3) == 0) {
                int lrow = mwarp + 16 * mt + 8 * hi + (lane >> 2);
                sP[(w & 1) * 128 + lrow] = p;
                sG[(w & 1) * 128 + lrow] = g;
            }
        }
        __syncthreads();
        if (tid < 128) {
            int m = m0 + tid;
            if (m < n) {
                g_p[m] = sP[tid] + sP[128 + tid];
                g_g[m] = (sG[tid] + sG[128 + tid]) * g_dinv[m];
            }
        }

        buf ^= 1;
        tile = next;
    }
}

// ---------------- layer-2 gather + output ----------------
// out[d] = sigmoid(p[d] - dinv[d] * sum_e g[src_e] + b2)
__global__ __launch_bounds__(256) void k_gather2(const float* __restrict__ b2,
                                                 float* __restrict__ out, int n) {
    int node = (blockIdx.x * blockDim.x + threadIdx.x) >> 5;
    int lane = threadIdx.x & 31;
    if (node >= n) return;
    int deg = __ldg(&g_cnt[node]);
    deg = (deg < CAP) ? deg : CAP;
    int beg = node * CAP;
    int end = beg + deg;
    float a = 0.f;
    for (int e = beg + lane; e < end; e += 32)
        a += __ldg(&g_g[__ldg(&g_slots[e])]);
    #pragma unroll
    for (int off = 16; off >= 1; off >>= 1)
        a += __shfl_xor_sync(0xffffffffu, a, off);
    if (lane == 0) {
        float z = __ldg(&g_p[node]) - __ldg(&g_dinv[node]) * a + b2[0];
        out[node] = 1.0f / (1.0f + expf(-z));
    }
}

extern "C" void kernel_launch(void* const* d_in, const int* in_sizes, int n_in,
                              void* d_out, int out_size) {
    const float* x   = (const float*)d_in[0];
    const int*   ei  = (const int*)d_in[1];
    const float* w10 = (const float*)d_in[2];
    const float* w11 = (const float*)d_in[3];
    const float* b1  = (const float*)d_in[4];
    const float* w20 = (const float*)d_in[5];
    const float* w21 = (const float*)d_in[6];
    const float* b2  = (const float*)d_in[7];
    float* out = (float*)d_out;

    int n = in_sizes[0] / 128;
    int E = in_sizes[1] / 2;
    const int* src = ei;
    const int* dst = ei + E;

    // zero the two counter arrays (memset nodes; no kernel needed)
    void* p_cnt = nullptr;
    void* p_srcdeg = nullptr;
    cudaGetSymbolAddress(&p_cnt, g_cnt);
    cudaGetSymbolAddress(&p_srcdeg, g_srcdeg);
    cudaMemsetAsync(p_cnt, 0, (size_t)n * sizeof(int));
    cudaMemsetAsync(p_srcdeg, 0, (size_t)n * sizeof(int));

    int pblocks = (E + 256 * PU - 1) / (256 * PU);
    k_placeconv<<<pblocks, 256>>>(x, w10, w11, src, dst, E, n);
    k_dinv<<<(n + 255) / 256, 256>>>(n);
    k_gather<<<(n * 32 + 255) / 256, 256>>>(n);

    cudaFuncSetAttribute(k_gemm, cudaFuncAttributeMaxDynamicSharedMemorySize,
                         SMEM_GEMM_BYTES);
    k_gemm<<<152, 256, SMEM_GEMM_BYTES>>>(b1, w20, w21, n);

    k_gather2<<<(n * 32 + 255) / 256, 256>>>(b2, out, n);
}